// round 1
// baseline (speedup 1.0000x reference)
#include <cuda_runtime.h>

// Problem constants (fixed shapes from reference)
#define BB 4
#define SS 8192
#define HH 16
#define DD 64
#define WW 128
#define CC 64            // SS / WW

constexpr int ROWS = 64;            // query rows per block (half a chunk)
constexpr int NT   = 256;           // threads per block

// smem strides (floats)
constexpr int QT_STRIDE = 68;       // sQT[d][row]   (Q transposed)
constexpr int KT_STRIDE = 132;      // sKT[d][kpos]  (K transposed)
constexpr int V_STRIDE  = 68;       // sV[kpos][d]   (V row-major)
constexpr int S_STRIDE  = 388;      // sS[row][col 0..383]

constexpr int SMEM_QT_F = DD * QT_STRIDE;     // 4352
constexpr int SMEM_KV_F = WW * V_STRIDE;      // 8704 (>= 64*132 = 8448 too)
constexpr int SMEM_S_F  = ROWS * S_STRIDE;    // 24832
constexpr int SMEM_BYTES = (SMEM_QT_F + SMEM_KV_F + SMEM_S_F) * 4;  // 151552

// ---- packed f32x2 helpers (sm_100+ FFMA2: 2x fp32 FMA throughput) ----
__device__ __forceinline__ unsigned long long pack2(float lo, float hi) {
    unsigned long long r;
    asm("mov.b64 %0, {%1, %2};" : "=l"(r) : "f"(lo), "f"(hi));
    return r;
}
__device__ __forceinline__ void fma2(unsigned long long& d,
                                     unsigned long long a, unsigned long long b) {
    asm("fma.rn.f32x2 %0, %1, %2, %0;" : "+l"(d) : "l"(a), "l"(b));
}
__device__ __forceinline__ void add2(unsigned long long& d, unsigned long long a) {
    asm("add.rn.f32x2 %0, %0, %1;" : "+l"(d) : "l"(a));
}

__global__ void __launch_bounds__(NT, 1)
swa_kernel(const float* __restrict__ q, const float* __restrict__ k,
           const float* __restrict__ v, float* __restrict__ out,
           float* __restrict__ attn)
{
    extern __shared__ float smem[];
    float* sQT = smem;                          // [DD][QT_STRIDE]
    float* sKV = smem + SMEM_QT_F;              // K^T or V (reused)
    float* sS  = smem + SMEM_QT_F + SMEM_KV_F;  // [ROWS][S_STRIDE]

    const int tid  = threadIdx.x;
    const int half = blockIdx.x & 1;
    const int c    = blockIdx.x >> 1;
    const int h    = blockIdx.y;
    const int b    = blockIdx.z;
    const int s0   = c * WW + half * ROWS;
    const size_t rowstride = (size_t)HH * DD;   // 1024 floats between seq positions

    // ---------------- load Q transposed into smem ----------------
    {
        const float* qbase = q + ((size_t)(b * SS + s0) * HH + h) * DD;
        const int r = tid >> 4, c4 = tid & 15;
        #pragma unroll
        for (int it = 0; it < 4; ++it) {
            int row = r + it * 16;
            float4 val = *(const float4*)(qbase + (size_t)row * rowstride + c4 * 4);
            int d0 = c4 * 4;
            sQT[(d0 + 0) * QT_STRIDE + row] = val.x;
            sQT[(d0 + 1) * QT_STRIDE + row] = val.y;
            sQT[(d0 + 2) * QT_STRIDE + row] = val.z;
            sQT[(d0 + 3) * QT_STRIDE + row] = val.w;
        }
    }

    // QK thread tile: ty in [0,16) -> rows 4ty..; tx in [0,16) -> cols {4tx..4tx+3, 64+4tx..64+4tx+3}
    const int ty = tid >> 4, tx = tid & 15;

    // ---------------- scores: S[64 x 384] ----------------
    for (int e = 0; e < 3; ++e) {
        const int ce = c + e - 1;
        __syncthreads();   // previous sKV use done; also orders Q stores before compute
        if (ce >= 0 && ce < CC) {
            // load K chunk transposed
            const float* kbase = k + ((size_t)(b * SS + ce * WW) * HH + h) * DD;
            const int r = tid >> 4, c4 = tid & 15;
            #pragma unroll
            for (int it = 0; it < 8; ++it) {
                int row = r + it * 16;   // key position 0..127
                float4 val = *(const float4*)(kbase + (size_t)row * rowstride + c4 * 4);
                int d0 = c4 * 4;
                sKV[(d0 + 0) * KT_STRIDE + row] = val.x;
                sKV[(d0 + 1) * KT_STRIDE + row] = val.y;
                sKV[(d0 + 2) * KT_STRIDE + row] = val.z;
                sKV[(d0 + 3) * KT_STRIDE + row] = val.w;
            }
            __syncthreads();

            unsigned long long acc2[4][4];
            #pragma unroll
            for (int i = 0; i < 4; ++i)
                #pragma unroll
                for (int j = 0; j < 4; ++j) acc2[i][j] = 0ULL;

            #pragma unroll 8
            for (int kd = 0; kd < DD; ++kd) {
                const float4 a = *(const float4*)&sQT[kd * QT_STRIDE + 4 * ty];
                const ulonglong2 bA = *(const ulonglong2*)&sKV[kd * KT_STRIDE + 4 * tx];
                const ulonglong2 bB = *(const ulonglong2*)&sKV[kd * KT_STRIDE + 64 + 4 * tx];
                unsigned long long bp[4] = { bA.x, bA.y, bB.x, bB.y };
                float av[4] = { a.x, a.y, a.z, a.w };
                #pragma unroll
                for (int i = 0; i < 4; ++i) {
                    unsigned long long aa = pack2(av[i], av[i]);
                    #pragma unroll
                    for (int j = 0; j < 4; ++j) fma2(acc2[i][j], aa, bp[j]);
                }
            }
            #pragma unroll
            for (int i = 0; i < 4; ++i) {
                int row = 4 * ty + i;
                ulonglong2 sA; sA.x = acc2[i][0]; sA.y = acc2[i][1];
                ulonglong2 sB; sB.x = acc2[i][2]; sB.y = acc2[i][3];
                *(ulonglong2*)&sS[row * S_STRIDE + e * WW + 4 * tx] = sA;
                *(ulonglong2*)&sS[row * S_STRIDE + e * WW + 64 + 4 * tx] = sB;
            }
        } else {
            // out-of-range neighbor chunk: scores are exactly 0 (padded K)
            ulonglong2 z; z.x = 0ULL; z.y = 0ULL;
            #pragma unroll
            for (int i = 0; i < 4; ++i) {
                int row = 4 * ty + i;
                *(ulonglong2*)&sS[row * S_STRIDE + e * WW + 4 * tx] = z;
                *(ulonglong2*)&sS[row * S_STRIDE + e * WW + 64 + 4 * tx] = z;
            }
        }
    }
    __syncthreads();

    // ---------------- softmax over 384 + write attn ----------------
    {
        const int warp = tid >> 5, lane = tid & 31;
        float* attnbase = attn + ((size_t)(b * SS + s0) * HH + h) * 384;
        for (int rr = 0; rr < 8; ++rr) {
            int row = warp * 8 + rr;
            float* srow = sS + row * S_STRIDE;
            float vals[12];
            float m = -3.4e38f;
            #pragma unroll
            for (int jj = 0; jj < 12; ++jj) {
                vals[jj] = srow[jj * 32 + lane];
                m = fmaxf(m, vals[jj]);
            }
            #pragma unroll
            for (int o = 16; o > 0; o >>= 1)
                m = fmaxf(m, __shfl_xor_sync(0xffffffffu, m, o));
            float sum = 0.f;
            #pragma unroll
            for (int jj = 0; jj < 12; ++jj) {
                float p = __expf(vals[jj] - m);
                vals[jj] = p;
                sum += p;
            }
            #pragma unroll
            for (int o = 16; o > 0; o >>= 1)
                sum += __shfl_xor_sync(0xffffffffu, sum, o);
            float inv = 1.0f / sum;
            float* grow = attnbase + (size_t)row * HH * 384;
            #pragma unroll
            for (int jj = 0; jj < 12; ++jj) {
                float p = vals[jj] * inv;
                srow[jj * 32 + lane] = p;   // for PV
                grow[jj * 32 + lane] = p;   // coalesced global write
            }
        }
    }
    __syncthreads();

    // ---------------- O = P @ V_ext  (kk split across 2 thread groups) ----------------
    const int g   = tid >> 7;          // 0/1: kk-half
    const int t   = tid & 127;
    const int tyO = t >> 3;            // 0..15 -> rows 4tyO..
    const int txO = t & 7;             // 0..7  -> cols {4txO.., 32+4txO..}
    const int colA = 4 * txO, colB = 32 + 4 * txO;

    unsigned long long accO2[4][4];
    #pragma unroll
    for (int i = 0; i < 4; ++i)
        #pragma unroll
        for (int j = 0; j < 4; ++j) accO2[i][j] = 0ULL;

    for (int e = 0; e < 3; ++e) {
        const int ce = c + e - 1;
        if (ce < 0 || ce >= CC) continue;   // padded V = 0 -> no contribution
        __syncthreads();                    // prior sKV readers done (also after softmax)
        {
            const float* vbase = v + ((size_t)(b * SS + ce * WW) * HH + h) * DD;
            const int r = tid >> 4, c4 = tid & 15;
            #pragma unroll
            for (int it = 0; it < 8; ++it) {
                int row = r + it * 16;
                float4 val = *(const float4*)(vbase + (size_t)row * rowstride + c4 * 4);
                *(float4*)&sKV[row * V_STRIDE + c4 * 4] = val;
            }
        }
        __syncthreads();

        #pragma unroll 8
        for (int kd = 0; kd < 64; ++kd) {
            int kk = g * 64 + kd;
            float a0 = sS[(4 * tyO + 0) * S_STRIDE + e * WW + kk];
            float a1 = sS[(4 * tyO + 1) * S_STRIDE + e * WW + kk];
            float a2 = sS[(4 * tyO + 2) * S_STRIDE + e * WW + kk];
            float a3 = sS[(4 * tyO + 3) * S_STRIDE + e * WW + kk];
            const ulonglong2 bA = *(const ulonglong2*)&sKV[kk * V_STRIDE + colA];
            const ulonglong2 bB = *(const ulonglong2*)&sKV[kk * V_STRIDE + colB];
            unsigned long long bp[4] = { bA.x, bA.y, bB.x, bB.y };
            float av[4] = { a0, a1, a2, a3 };
            #pragma unroll
            for (int i = 0; i < 4; ++i) {
                unsigned long long aa = pack2(av[i], av[i]);
                #pragma unroll
                for (int j = 0; j < 4; ++j) fma2(accO2[i][j], aa, bp[j]);
            }
        }
    }
    __syncthreads();   // all sS / sKV reads done

    // group 1 dumps partials into (reused) sS, group 0 reduces + writes out
    float* sRed = sS;  // stride 68, rows 0..63, cols 0..63
    if (g == 1) {
        #pragma unroll
        for (int i = 0; i < 4; ++i) {
            int row = 4 * tyO + i;
            ulonglong2 sA; sA.x = accO2[i][0]; sA.y = accO2[i][1];
            ulonglong2 sB; sB.x = accO2[i][2]; sB.y = accO2[i][3];
            *(ulonglong2*)&sRed[row * 68 + colA] = sA;
            *(ulonglong2*)&sRed[row * 68 + colB] = sB;
        }
    }
    __syncthreads();
    if (g == 0) {
        float* obase = out + ((size_t)(b * SS + s0) * HH + h) * DD;
        #pragma unroll
        for (int i = 0; i < 4; ++i) {
            int row = 4 * tyO + i;
            ulonglong2 pA = *(const ulonglong2*)&sRed[row * 68 + colA];
            ulonglong2 pB = *(const ulonglong2*)&sRed[row * 68 + colB];
            add2(accO2[i][0], pA.x);
            add2(accO2[i][1], pA.y);
            add2(accO2[i][2], pB.x);
            add2(accO2[i][3], pB.y);
            ulonglong2 oA; oA.x = accO2[i][0]; oA.y = accO2[i][1];
            ulonglong2 oB; oB.x = accO2[i][2]; oB.y = accO2[i][3];
            *(ulonglong2*)(obase + (size_t)row * rowstride + colA) = oA;
            *(ulonglong2*)(obase + (size_t)row * rowstride + colB) = oB;
        }
    }
}

extern "C" void kernel_launch(void* const* d_in, const int* in_sizes, int n_in,
                              void* d_out, int out_size) {
    const float* q = (const float*)d_in[0];
    const float* k = (const float*)d_in[1];
    const float* v = (const float*)d_in[2];
    float* out  = (float*)d_out;
    float* attn = out + (size_t)BB * SS * HH * DD;   // tuple order: (out, attn)

    cudaFuncSetAttribute(swa_kernel, cudaFuncAttributeMaxDynamicSharedMemorySize,
                         SMEM_BYTES);
    dim3 grid(CC * 2, HH, BB);
    swa_kernel<<<grid, NT, SMEM_BYTES>>>(q, k, v, out, attn);
}

// round 3
// speedup vs baseline: 1.0002x; 1.0002x over previous
#include <cuda_runtime.h>

// Problem constants (fixed shapes from reference)
#define BB 4
#define SS 8192
#define HH 16
#define DD 64
#define WW 128
#define CC 64            // SS / WW

constexpr int ROWS = 64;            // query rows per block (half a chunk)
constexpr int NT   = 256;           // threads per block

// smem strides (floats)
constexpr int QT_STRIDE = 68;       // sQT[d][row]   (Q transposed)
constexpr int KT_STRIDE = 132;      // sKT[d][kpos]  (K transposed)
constexpr int V_STRIDE  = 68;       // sV[kpos][d]   (V row-major)
constexpr int S_STRIDE  = 388;      // sS[row][col 0..383]

constexpr int SMEM_QT_F = DD * QT_STRIDE;     // 4352
constexpr int SMEM_KV_F = WW * V_STRIDE;      // 8704 (>= 64*132 = 8448 too)
constexpr int SMEM_S_F  = ROWS * S_STRIDE;    // 24832
constexpr int SMEM_BYTES = (SMEM_QT_F + SMEM_KV_F + SMEM_S_F) * 4;  // 151552

// ---- packed f32x2 helpers (sm_100+ FFMA2: 2x fp32 FMA throughput) ----
__device__ __forceinline__ unsigned long long pack2(float lo, float hi) {
    unsigned long long r;
    asm("mov.b64 %0, {%1, %2};" : "=l"(r) : "f"(lo), "f"(hi));
    return r;
}
__device__ __forceinline__ void fma2(unsigned long long& d,
                                     unsigned long long a, unsigned long long b) {
    asm("fma.rn.f32x2 %0, %1, %2, %0;" : "+l"(d) : "l"(a), "l"(b));
}
__device__ __forceinline__ void add2(unsigned long long& d, unsigned long long a) {
    asm("add.rn.f32x2 %0, %0, %1;" : "+l"(d) : "l"(a));
}

__global__ void __launch_bounds__(NT, 1)
swa_kernel(const float* __restrict__ q, const float* __restrict__ k,
           const float* __restrict__ v, float* __restrict__ out,
           float* __restrict__ attn)
{
    extern __shared__ float smem[];
    float* sQT = smem;                          // [DD][QT_STRIDE]
    float* sKV = smem + SMEM_QT_F;              // K^T or V (reused)
    float* sS  = smem + SMEM_QT_F + SMEM_KV_F;  // [ROWS][S_STRIDE]

    const int tid  = threadIdx.x;
    const int half = blockIdx.x & 1;
    const int c    = blockIdx.x >> 1;
    const int h    = blockIdx.y;
    const int b    = blockIdx.z;
    const int s0   = c * WW + half * ROWS;
    const size_t rowstride = (size_t)HH * DD;   // 1024 floats between seq positions

    // ---------------- load Q transposed into smem ----------------
    {
        const float* qbase = q + ((size_t)(b * SS + s0) * HH + h) * DD;
        const int r = tid >> 4, c4 = tid & 15;
        #pragma unroll
        for (int it = 0; it < 4; ++it) {
            int row = r + it * 16;
            float4 val = *(const float4*)(qbase + (size_t)row * rowstride + c4 * 4);
            int d0 = c4 * 4;
            sQT[(d0 + 0) * QT_STRIDE + row] = val.x;
            sQT[(d0 + 1) * QT_STRIDE + row] = val.y;
            sQT[(d0 + 2) * QT_STRIDE + row] = val.z;
            sQT[(d0 + 3) * QT_STRIDE + row] = val.w;
        }
    }

    // QK thread tile: ty in [0,16) -> rows 4ty..; tx in [0,16) -> cols {4tx..4tx+3, 64+4tx..64+4tx+3}
    const int ty = tid >> 4, tx = tid & 15;

    // ---------------- scores: S[64 x 384] ----------------
    for (int e = 0; e < 3; ++e) {
        const int ce = c + e - 1;
        __syncthreads();   // previous sKV use done; also orders Q stores before compute
        if (ce >= 0 && ce < CC) {
            // load K chunk transposed
            const float* kbase = k + ((size_t)(b * SS + ce * WW) * HH + h) * DD;
            const int r = tid >> 4, c4 = tid & 15;
            #pragma unroll
            for (int it = 0; it < 8; ++it) {
                int row = r + it * 16;   // key position 0..127
                float4 val = *(const float4*)(kbase + (size_t)row * rowstride + c4 * 4);
                int d0 = c4 * 4;
                sKV[(d0 + 0) * KT_STRIDE + row] = val.x;
                sKV[(d0 + 1) * KT_STRIDE + row] = val.y;
                sKV[(d0 + 2) * KT_STRIDE + row] = val.z;
                sKV[(d0 + 3) * KT_STRIDE + row] = val.w;
            }
            __syncthreads();

            unsigned long long acc2[4][4];
            #pragma unroll
            for (int i = 0; i < 4; ++i)
                #pragma unroll
                for (int j = 0; j < 4; ++j) acc2[i][j] = 0ULL;

            #pragma unroll 8
            for (int kd = 0; kd < DD; ++kd) {
                const float4 a = *(const float4*)&sQT[kd * QT_STRIDE + 4 * ty];
                const ulonglong2 bA = *(const ulonglong2*)&sKV[kd * KT_STRIDE + 4 * tx];
                const ulonglong2 bB = *(const ulonglong2*)&sKV[kd * KT_STRIDE + 64 + 4 * tx];
                unsigned long long bp[4] = { bA.x, bA.y, bB.x, bB.y };
                float av[4] = { a.x, a.y, a.z, a.w };
                #pragma unroll
                for (int i = 0; i < 4; ++i) {
                    unsigned long long aa = pack2(av[i], av[i]);
                    #pragma unroll
                    for (int j = 0; j < 4; ++j) fma2(acc2[i][j], aa, bp[j]);
                }
            }
            #pragma unroll
            for (int i = 0; i < 4; ++i) {
                int row = 4 * ty + i;
                ulonglong2 sA; sA.x = acc2[i][0]; sA.y = acc2[i][1];
                ulonglong2 sB; sB.x = acc2[i][2]; sB.y = acc2[i][3];
                *(ulonglong2*)&sS[row * S_STRIDE + e * WW + 4 * tx] = sA;
                *(ulonglong2*)&sS[row * S_STRIDE + e * WW + 64 + 4 * tx] = sB;
            }
        } else {
            // out-of-range neighbor chunk: scores are exactly 0 (padded K)
            ulonglong2 z; z.x = 0ULL; z.y = 0ULL;
            #pragma unroll
            for (int i = 0; i < 4; ++i) {
                int row = 4 * ty + i;
                *(ulonglong2*)&sS[row * S_STRIDE + e * WW + 4 * tx] = z;
                *(ulonglong2*)&sS[row * S_STRIDE + e * WW + 64 + 4 * tx] = z;
            }
        }
    }
    __syncthreads();

    // ---------------- softmax over 384 + write attn ----------------
    {
        const int warp = tid >> 5, lane = tid & 31;
        float* attnbase = attn + ((size_t)(b * SS + s0) * HH + h) * 384;
        for (int rr = 0; rr < 8; ++rr) {
            int row = warp * 8 + rr;
            float* srow = sS + row * S_STRIDE;
            float vals[12];
            float m = -3.4e38f;
            #pragma unroll
            for (int jj = 0; jj < 12; ++jj) {
                vals[jj] = srow[jj * 32 + lane];
                m = fmaxf(m, vals[jj]);
            }
            #pragma unroll
            for (int o = 16; o > 0; o >>= 1)
                m = fmaxf(m, __shfl_xor_sync(0xffffffffu, m, o));
            float sum = 0.f;
            #pragma unroll
            for (int jj = 0; jj < 12; ++jj) {
                float p = __expf(vals[jj] - m);
                vals[jj] = p;
                sum += p;
            }
            #pragma unroll
            for (int o = 16; o > 0; o >>= 1)
                sum += __shfl_xor_sync(0xffffffffu, sum, o);
            float inv = 1.0f / sum;
            float* grow = attnbase + (size_t)row * HH * 384;
            #pragma unroll
            for (int jj = 0; jj < 12; ++jj) {
                float p = vals[jj] * inv;
                srow[jj * 32 + lane] = p;   // for PV
                grow[jj * 32 + lane] = p;   // coalesced global write
            }
        }
    }
    __syncthreads();

    // ---------------- O = P @ V_ext  (kk split across 2 thread groups) ----------------
    const int g   = tid >> 7;          // 0/1: kk-half
    const int t   = tid & 127;
    const int tyO = t >> 3;            // 0..15 -> rows 4tyO..
    const int txO = t & 7;             // 0..7  -> cols {4txO.., 32+4txO..}
    const int colA = 4 * txO, colB = 32 + 4 * txO;

    unsigned long long accO2[4][4];
    #pragma unroll
    for (int i = 0; i < 4; ++i)
        #pragma unroll
        for (int j = 0; j < 4; ++j) accO2[i][j] = 0ULL;

    for (int e = 0; e < 3; ++e) {
        const int ce = c + e - 1;
        if (ce < 0 || ce >= CC) continue;   // padded V = 0 -> no contribution
        __syncthreads();                    // prior sKV readers done (also after softmax)
        {
            const float* vbase = v + ((size_t)(b * SS + ce * WW) * HH + h) * DD;
            const int r = tid >> 4, c4 = tid & 15;
            #pragma unroll
            for (int it = 0; it < 8; ++it) {
                int row = r + it * 16;
                float4 val = *(const float4*)(vbase + (size_t)row * rowstride + c4 * 4);
                *(float4*)&sKV[row * V_STRIDE + c4 * 4] = val;
            }
        }
        __syncthreads();

        #pragma unroll 8
        for (int kd = 0; kd < 64; ++kd) {
            int kk = g * 64 + kd;
            float a0 = sS[(4 * tyO + 0) * S_STRIDE + e * WW + kk];
            float a1 = sS[(4 * tyO + 1) * S_STRIDE + e * WW + kk];
            float a2 = sS[(4 * tyO + 2) * S_STRIDE + e * WW + kk];
            float a3 = sS[(4 * tyO + 3) * S_STRIDE + e * WW + kk];
            const ulonglong2 bA = *(const ulonglong2*)&sKV[kk * V_STRIDE + colA];
            const ulonglong2 bB = *(const ulonglong2*)&sKV[kk * V_STRIDE + colB];
            unsigned long long bp[4] = { bA.x, bA.y, bB.x, bB.y };
            float av[4] = { a0, a1, a2, a3 };
            #pragma unroll
            for (int i = 0; i < 4; ++i) {
                unsigned long long aa = pack2(av[i], av[i]);
                #pragma unroll
                for (int j = 0; j < 4; ++j) fma2(accO2[i][j], aa, bp[j]);
            }
        }
    }
    __syncthreads();   // all sS / sKV reads done

    // group 1 dumps partials into (reused) sS, group 0 reduces + writes out
    float* sRed = sS;  // stride 68, rows 0..63, cols 0..63
    if (g == 1) {
        #pragma unroll
        for (int i = 0; i < 4; ++i) {
            int row = 4 * tyO + i;
            ulonglong2 sA; sA.x = accO2[i][0]; sA.y = accO2[i][1];
            ulonglong2 sB; sB.x = accO2[i][2]; sB.y = accO2[i][3];
            *(ulonglong2*)&sRed[row * 68 + colA] = sA;
            *(ulonglong2*)&sRed[row * 68 + colB] = sB;
        }
    }
    __syncthreads();
    if (g == 0) {
        float* obase = out + ((size_t)(b * SS + s0) * HH + h) * DD;
        #pragma unroll
        for (int i = 0; i < 4; ++i) {
            int row = 4 * tyO + i;
            ulonglong2 pA = *(const ulonglong2*)&sRed[row * 68 + colA];
            ulonglong2 pB = *(const ulonglong2*)&sRed[row * 68 + colB];
            add2(accO2[i][0], pA.x);
            add2(accO2[i][1], pA.y);
            add2(accO2[i][2], pB.x);
            add2(accO2[i][3], pB.y);
            ulonglong2 oA; oA.x = accO2[i][0]; oA.y = accO2[i][1];
            ulonglong2 oB; oB.x = accO2[i][2]; oB.y = accO2[i][3];
            *(ulonglong2*)(obase + (size_t)row * rowstride + colA) = oA;
            *(ulonglong2*)(obase + (size_t)row * rowstride + colB) = oB;
        }
    }
}

extern "C" void kernel_launch(void* const* d_in, const int* in_sizes, int n_in,
                              void* d_out, int out_size) {
    const float* q = (const float*)d_in[0];
    const float* k = (const float*)d_in[1];
    const float* v = (const float*)d_in[2];
    float* out  = (float*)d_out;
    float* attn = out + (size_t)BB * SS * HH * DD;   // tuple order: (out, attn)

    cudaFuncSetAttribute(swa_kernel, cudaFuncAttributeMaxDynamicSharedMemorySize,
                         SMEM_BYTES);
    dim3 grid(CC * 2, HH, BB);
    swa_kernel<<<grid, NT, SMEM_BYTES>>>(q, k, v, out, attn);
}

// round 7
// speedup vs baseline: 2.0868x; 2.0864x over previous
#include <cuda_runtime.h>
#include <cstdint>

#define BB 4
#define SS 8192
#define HH 16
#define DD 64
#define WW 128
#define CC 64

constexpr int NT = 256;

// bf16 tiles [128 rows][64 cols], row stride 72 halves (144B -> ldmatrix conflict-free)
constexpr int TILE_B = 128 * 144;         // 18432 bytes per (hi or lo) tile
constexpr int OFF_QH = 0;
constexpr int OFF_QL = OFF_QH + TILE_B;
constexpr int OFF_KH = OFF_QL + TILE_B;   // lo always at +TILE_B from hi
constexpr int OFF_KL = OFF_KH + TILE_B;
constexpr int OFF_VH = OFF_KL + TILE_B;
constexpr int OFF_VL = OFF_VH + TILE_B;
constexpr int SMEM_BYTES = OFF_VL + TILE_B;   // 110592 -> 2 CTAs/SM

__device__ __forceinline__ uint32_t smem_u32(const void* p) {
    uint32_t a;
    asm("{ .reg .u64 t; cvta.to.shared.u64 t, %1; cvt.u32.u64 %0, t; }" : "=r"(a) : "l"(p));
    return a;
}
__device__ __forceinline__ uint32_t cvt_bf16x2(float up, float lo) {   // {hi16=up, lo16=lo}
    uint32_t r;
    asm("cvt.rn.bf16x2.f32 %0, %1, %2;" : "=r"(r) : "f"(up), "f"(lo));
    return r;
}
__device__ __forceinline__ void ldm4(uint32_t r[4], uint32_t a) {
    asm volatile("ldmatrix.sync.aligned.m8n8.x4.shared.b16 {%0,%1,%2,%3}, [%4];"
                 : "=r"(r[0]), "=r"(r[1]), "=r"(r[2]), "=r"(r[3]) : "r"(a));
}
__device__ __forceinline__ void ldm4t(uint32_t r[4], uint32_t a) {
    asm volatile("ldmatrix.sync.aligned.m8n8.x4.trans.shared.b16 {%0,%1,%2,%3}, [%4];"
                 : "=r"(r[0]), "=r"(r[1]), "=r"(r[2]), "=r"(r[3]) : "r"(a));
}
__device__ __forceinline__ void mma16816(float c[4], const uint32_t a[4],
                                         uint32_t b0, uint32_t b1) {
    asm volatile("mma.sync.aligned.m16n8k16.row.col.f32.bf16.bf16.f32 "
                 "{%0,%1,%2,%3}, {%4,%5,%6,%7}, {%8,%9}, {%0,%1,%2,%3};"
                 : "+f"(c[0]), "+f"(c[1]), "+f"(c[2]), "+f"(c[3])
                 : "r"(a[0]), "r"(a[1]), "r"(a[2]), "r"(a[3]), "r"(b0), "r"(b1));
}

// FMA-pipe exp (avoids MUFU bottleneck). |x| <= ~90 here; rel err ~3e-6.
__device__ __forceinline__ float fexp(float x) {
    float t = x * 1.4426950408889634f;
    float r = __fadd_rn(t, 12582912.0f);        // round-to-nearest-int trick
    float n = __fsub_rn(r, 12582912.0f);
    float f = __fsub_rn(t, n);
    float p = 1.3333558e-3f;
    p = fmaf(p, f, 9.6181291e-3f);
    p = fmaf(p, f, 5.5504109e-2f);
    p = fmaf(p, f, 2.4022651e-1f);
    p = fmaf(p, f, 6.9314718e-1f);
    p = fmaf(p, f, 1.0f);
    int e = (int)n;
    return __int_as_float(__float_as_int(p) + (e << 23));
}

// gmem fp32 [128 rows x 64] -> smem bf16 hi/lo tiles (lo at dstH + TILE_B)
__device__ __forceinline__ void load_split(char* smc, int dstH, const float* gbase, int tid) {
    #pragma unroll
    for (int it = 0; it < 8; ++it) {
        int idx = tid + it * 256;
        int r = idx >> 4, d0 = (idx & 15) << 2;
        float4 t = *(const float4*)(gbase + (size_t)r * 1024 + d0);
        uint32_t h0 = cvt_bf16x2(t.y, t.x);
        uint32_t h1 = cvt_bf16x2(t.w, t.z);
        float f0 = __uint_as_float(h0 << 16);
        float f1 = __uint_as_float(h0 & 0xffff0000u);
        float f2 = __uint_as_float(h1 << 16);
        float f3 = __uint_as_float(h1 & 0xffff0000u);
        uint32_t l0 = cvt_bf16x2(t.y - f1, t.x - f0);
        uint32_t l1 = cvt_bf16x2(t.w - f3, t.z - f2);
        int off = r * 144 + d0 * 2;
        *(uint2*)(smc + dstH + off) = make_uint2(h0, h1);
        *(uint2*)(smc + dstH + TILE_B + off) = make_uint2(l0, l1);
    }
}

// S tile [16 rows x 64 cols]: 3-product bf16 split QK. qBase/kBase2 are lane-adjusted.
__device__ __forceinline__ void qk_tile(float pc[8][4], uint32_t qBase, uint32_t kBase2) {
    #pragma unroll
    for (int ks = 0; ks < 4; ++ks) {
        uint32_t qh[4], ql[4];
        ldm4(qh, qBase + ks * 32);
        ldm4(ql, qBase + TILE_B + ks * 32);
        #pragma unroll
        for (int np = 0; np < 4; ++np) {
            uint32_t kh[4], kl[4];
            uint32_t ka = kBase2 + np * (16 * 144) + ks * 32;
            ldm4(kh, ka);
            ldm4(kl, ka + TILE_B);
            mma16816(pc[2*np],   qh, kh[0], kh[1]);
            mma16816(pc[2*np],   qh, kl[0], kl[1]);
            mma16816(pc[2*np],   ql, kh[0], kh[1]);
            mma16816(pc[2*np+1], qh, kh[2], kh[3]);
            mma16816(pc[2*np+1], qh, kl[2], kl[3]);
            mma16816(pc[2*np+1], ql, kh[2], kh[3]);
        }
    }
}

// O += P(unnormalized exp, in C-frag regs) @ V, 3-product split; P->A frag in registers
__device__ __forceinline__ void pv_tile(float o[8][4], const float pc[8][4], uint32_t vBase2) {
    #pragma unroll
    for (int kt = 0; kt < 4; ++kt) {
        uint32_t ahi[4], alo[4];
        #pragma unroll
        for (int hf = 0; hf < 2; ++hf) {
            const float* s = pc[2 * kt + hf];
            uint32_t hA = cvt_bf16x2(s[1], s[0]);
            uint32_t hB = cvt_bf16x2(s[3], s[2]);
            float l0 = s[0] - __uint_as_float(hA << 16);
            float l1 = s[1] - __uint_as_float(hA & 0xffff0000u);
            float l2 = s[2] - __uint_as_float(hB << 16);
            float l3 = s[3] - __uint_as_float(hB & 0xffff0000u);
            ahi[2*hf+0] = hA;                 ahi[2*hf+1] = hB;
            alo[2*hf+0] = cvt_bf16x2(l1, l0); alo[2*hf+1] = cvt_bf16x2(l3, l2);
        }
        #pragma unroll
        for (int dp = 0; dp < 4; ++dp) {
            uint32_t vh[4], vl[4];
            uint32_t va = vBase2 + kt * (16 * 144) + dp * 32;
            ldm4t(vh, va);
            ldm4t(vl, va + TILE_B);
            mma16816(o[2*dp],   ahi, vh[0], vh[1]);
            mma16816(o[2*dp],   ahi, vl[0], vl[1]);
            mma16816(o[2*dp],   alo, vh[0], vh[1]);
            mma16816(o[2*dp+1], ahi, vh[2], vh[3]);
            mma16816(o[2*dp+1], ahi, vl[2], vl[3]);
            mma16816(o[2*dp+1], alo, vh[2], vh[3]);
        }
    }
}

__global__ void __launch_bounds__(NT, 2)
swa_mma(const float* __restrict__ q, const float* __restrict__ k,
        const float* __restrict__ v, float* __restrict__ out,
        float* __restrict__ attn)
{
    extern __shared__ char smc[];
    const uint32_t sb = smem_u32(smc);
    const int tid = threadIdx.x;
    const int w = tid >> 5, ln = tid & 31;
    const int c = blockIdx.x, h = blockIdx.y, b = blockIdx.z;
    const int s0 = c * WW;
    const int rw = w * 16;                      // warp's first query row

    // lane-dependent ldmatrix base offsets
    const uint32_t qBase = sb + OFF_QH + (rw + (ln & 15)) * 144 + ((ln >> 4) & 1) * 16;
    const uint32_t kLane = (ln & 7) * 144 + ((ln >> 4) & 1) * (8 * 144) + ((ln >> 3) & 1) * 16;
    const uint32_t vLane = (ln & 7) * 144 + ((ln >> 3) & 1) * (8 * 144) + ((ln >> 4) & 1) * 16;

    // load Q (hi/lo) once
    load_split(smc, OFF_QH, q + ((size_t)(b * SS + s0) * HH + h) * DD, tid);
    __syncthreads();

    float o[8][4];
    #pragma unroll
    for (int i = 0; i < 8; ++i)
        #pragma unroll
        for (int j = 0; j < 4; ++j) o[i][j] = 0.f;
    float s0sum = 0.f, s1sum = 0.f;
    int ninv = 0;

    // ---------------- pass 1: QK -> exp -> rowsums + unnormalized PV ----------------
    for (int e = 0; e < 3; ++e) {
        const int ce = c + e - 1;
        if ((unsigned)ce >= (unsigned)CC) { ++ninv; continue; }
        __syncthreads();   // prior K/V reads complete before overwrite
        load_split(smc, OFF_KH, k + ((size_t)(b * SS + ce * WW) * HH + h) * DD, tid);
        load_split(smc, OFF_VH, v + ((size_t)(b * SS + ce * WW) * HH + h) * DD, tid);
        __syncthreads();
        for (int h2 = 0; h2 < 2; ++h2) {
            float pc[8][4];
            #pragma unroll
            for (int i = 0; i < 8; ++i)
                #pragma unroll
                for (int j = 0; j < 4; ++j) pc[i][j] = 0.f;
            qk_tile(pc, qBase, sb + OFF_KH + kLane + h2 * (64 * 144));
            #pragma unroll
            for (int p = 0; p < 8; ++p) {
                pc[p][0] = fexp(pc[p][0]); pc[p][1] = fexp(pc[p][1]);
                pc[p][2] = fexp(pc[p][2]); pc[p][3] = fexp(pc[p][3]);
                s0sum += pc[p][0] + pc[p][1];
                s1sum += pc[p][2] + pc[p][3];
            }
            pv_tile(o, pc, sb + OFF_VH + vLane + h2 * (64 * 144));
        }
    }
    // row sums: reduce across the 4 lanes sharing a row
    s0sum += __shfl_xor_sync(0xffffffffu, s0sum, 1);
    s0sum += __shfl_xor_sync(0xffffffffu, s0sum, 2);
    s1sum += __shfl_xor_sync(0xffffffffu, s1sum, 1);
    s1sum += __shfl_xor_sync(0xffffffffu, s1sum, 2);
    s0sum += 128.0f * ninv;          // padded chunks contribute exp(0)=1 per column
    s1sum += 128.0f * ninv;
    const float inv0 = 1.0f / s0sum;
    const float inv1 = 1.0f / s1sum;

    // ---------------- pass 2: recompute QK -> exp -> normalized attn ----------------
    const int r0g = rw + (ln >> 2);
    float* arow0 = attn + ((size_t)(b * SS + s0 + r0g) * HH + h) * 384 + 2 * (ln & 3);
    float* arow1 = arow0 + (size_t)8 * HH * 384;
    for (int e = 0; e < 3; ++e) {
        const int ce = c + e - 1;
        if ((unsigned)ce < (unsigned)CC) {
            __syncthreads();
            load_split(smc, OFF_KH, k + ((size_t)(b * SS + ce * WW) * HH + h) * DD, tid);
            __syncthreads();
            for (int h2 = 0; h2 < 2; ++h2) {
                float pc[8][4];
                #pragma unroll
                for (int i = 0; i < 8; ++i)
                    #pragma unroll
                    for (int j = 0; j < 4; ++j) pc[i][j] = 0.f;
                qk_tile(pc, qBase, sb + OFF_KH + kLane + h2 * (64 * 144));
                #pragma unroll
                for (int p = 0; p < 8; ++p) {
                    int col = e * 128 + h2 * 64 + p * 8;
                    *(float2*)(arow0 + col) =
                        make_float2(fexp(pc[p][0]) * inv0, fexp(pc[p][1]) * inv0);
                    *(float2*)(arow1 + col) =
                        make_float2(fexp(pc[p][2]) * inv1, fexp(pc[p][3]) * inv1);
                }
            }
        } else {
            const float2 f0 = make_float2(inv0, inv0);
            const float2 f1 = make_float2(inv1, inv1);
            #pragma unroll
            for (int p8 = 0; p8 < 16; ++p8) {
                int col = e * 128 + p8 * 8;
                *(float2*)(arow0 + col) = f0;
                *(float2*)(arow1 + col) = f1;
            }
        }
    }

    // ---------------- O = O_unnorm * inv, store ----------------
    {
        float* orow0 = out + ((size_t)(b * SS + s0 + r0g) * HH + h) * DD + 2 * (ln & 3);
        float* orow1 = orow0 + (size_t)8 * HH * DD;
        #pragma unroll
        for (int dt = 0; dt < 8; ++dt) {
            *(float2*)(orow0 + dt * 8) = make_float2(o[dt][0] * inv0, o[dt][1] * inv0);
            *(float2*)(orow1 + dt * 8) = make_float2(o[dt][2] * inv1, o[dt][3] * inv1);
        }
    }
}

extern "C" void kernel_launch(void* const* d_in, const int* in_sizes, int n_in,
                              void* d_out, int out_size) {
    const float* q = (const float*)d_in[0];
    const float* k = (const float*)d_in[1];
    const float* v = (const float*)d_in[2];
    float* out  = (float*)d_out;
    float* attn = out + (size_t)BB * SS * HH * DD;   // tuple order: (out, attn)

    cudaFuncSetAttribute(swa_mma, cudaFuncAttributeMaxDynamicSharedMemorySize, SMEM_BYTES);
    dim3 grid(CC, HH, BB);
    swa_mma<<<grid, NT, SMEM_BYTES>>>(q, k, v, out, attn);
}